// round 12
// baseline (speedup 1.0000x reference)
#include <cuda_runtime.h>
#include <cstdint>

#define T_DIM   8192
#define C_DIM   8
#define CAP     288
#define NT      256
#define NWARPS  (NT / 32)
#define DEPTH   2
#define NVEC    (T_DIM * C_DIM / 4)    // 16384 float4 per batch row
#define GROUPS  (NVEC / (NT * DEPTH))  // 32
#define RANK0   7371                   // floor(0.9 * (T_DIM-1))
#define LO_B    0x3F9AE140             // bits of ~1.21f (32-ulp aligned)
#define RANGE_BITS 0x130000            // window width in ulps -> HI ~ 1.3506f
#define SLOTS   12                     // u16 slots per thread-channel

typedef unsigned long long ull;

__device__ __constant__ float kFrac = (float)(0.9 * (double)(T_DIM - 1) - (double)RANK0);

struct Sm {
    uint16_t priv[NT][4][SLOTS];    // 24 KB contiguous per-thread capture slots
    uint16_t cand[C_DIM][CAP];      // 4.5 KB compacted u16 keys
    uint32_t cntp[NT];              // packed per-thread per-channel hit counts
    float    wpart[NWARPS][C_DIM][3];
    int      wbelow[NWARPS][C_DIM];
    float    stat[C_DIM][4];
    int      below[C_DIM];
    int      fb[C_DIM];
    int      fball;                 // CTA-wide overflow flag -> full exact fallback
    int      bcast[2];
};

__device__ __forceinline__ float key_to_float(int key) {
    return __int_as_float((int)LO_B + (key << 5) + 16);   // bucket midpoint, <=16 ulp err
}

__device__ __forceinline__ uint32_t fkey(float v) {
    uint32_t u = __float_as_uint(v);
    return (u & 0x80000000u) ? ~u : (u | 0x80000000u);
}
__device__ __forceinline__ float fkey_inv(uint32_t k) {
    uint32_t u = (k & 0x80000000u) ? (k ^ 0x80000000u) : ~k;
    return __uint_as_float(u);
}

// fused hot path, compile-time channel J. 10 instructions:
//   d = vb - LO_B
//   pkbel += (d<0)<<8J ; pkpos += (vb>0)<<8J
//   if ((uint)d < RANGE_BITS) { st.shared.u16 (d>>5); addr += 2 }   (no bound guard)
template <int J>
__device__ __forceinline__ void capture(int vb, uint32_t& addr,
                                        uint32_t& pkbel, uint32_t& pkpos) {
    asm volatile(
        "{\n\t"
        ".reg .pred plo, pw, pp;\n\t"
        ".reg .b32 d;\n\t"
        ".reg .b16 h;\n\t"
        "sub.s32 d, %3, %4;\n\t"
        "setp.lt.s32 plo, d, 0;\n\t"
        "setp.lt.u32 pw, d, %5;\n\t"
        "@plo add.s32 %1, %1, %6;\n\t"
        "setp.gt.s32 pp, %3, 0;\n\t"
        "@pp add.s32 %2, %2, %6;\n\t"
        "shr.u32 d, d, 5;\n\t"
        "cvt.u16.u32 h, d;\n\t"
        "@pw st.shared.u16 [%0], h;\n\t"
        "@pw add.s32 %0, %0, 2;\n\t"
        "}"
        : "+r"(addr), "+r"(pkbel), "+r"(pkpos)
        : "r"(vb), "n"((int)LO_B), "n"(RANGE_BITS), "n"(1 << (8 * J)));
}

// Exact rank-r select over n u16 keys; one warp, 2-pass byte radix.
__device__ int warp_select16(const uint16_t* cand, uint32_t* hist, int n, int r) {
    const int lane = threadIdx.x & 31;
    int hibin = -1;
    for (int pass = 0; pass < 2; pass++) {
        for (int i = lane; i < 256; i += 32) hist[i] = 0;
        __syncwarp();
        for (int i = lane; i < n; i += 32) {
            uint32_t k = cand[i];
            if (pass == 0) atomicAdd(&hist[k >> 8], 1u);
            else if ((int)(k >> 8) == hibin) atomicAdd(&hist[k & 255u], 1u);
        }
        __syncwarp();
        uint32_t bv[8];
        uint32_t loc = 0;
#pragma unroll
        for (int j = 0; j < 8; j++) { bv[j] = hist[lane * 8 + j]; loc += bv[j]; }
        uint32_t pre = loc;
#pragma unroll
        for (int d = 1; d < 32; d <<= 1) {
            uint32_t t = __shfl_up_sync(0xffffffffu, pre, d);
            if (lane >= d) pre += t;
        }
        int excl = (int)(pre - loc);
        bool myfind = (r >= excl) && (r < excl + (int)loc);
        uint32_t ball = __ballot_sync(0xffffffffu, myfind);
        int src = __ffs(ball) - 1;
        int bin_out = 0, rem_out = 0;
        if (myfind) {
            int rem = r - excl, bsel = 0;
            bool found = false;
#pragma unroll
            for (int j = 0; j < 8; j++) {
                if (!found) {
                    if (rem < (int)bv[j]) { bsel = j; found = true; }
                    else rem -= (int)bv[j];
                }
            }
            bin_out = lane * 8 + bsel;
            rem_out = rem;
        }
        int bin = __shfl_sync(0xffffffffu, bin_out, src);
        r       = __shfl_sync(0xffffffffu, rem_out, src);
        if (pass == 0) hibin = bin;
        else           hibin = (hibin << 8) | bin;
        __syncwarp();
    }
    return hibin;   // full 16-bit key
}

// Block-wide exact rank-r selection from global (fallback; rare).
__device__ float block_select_global(const float* __restrict__ x, int b, int c, int r,
                                     uint32_t* hist, int* bcast) {
    const int tid = threadIdx.x;
    uint32_t prefix = 0, done = 0;
    for (int shift = 24; shift >= 0; shift -= 8) {
        for (int i = tid; i < 256; i += NT) hist[i] = 0;
        __syncthreads();
        for (int t = tid; t < T_DIM; t += NT) {
            float v = x[((size_t)b * T_DIM + t) * C_DIM + c];
            uint32_t k = fkey(v);
            if ((k & done) == prefix) atomicAdd(&hist[(k >> shift) & 255u], 1u);
        }
        __syncthreads();
        if (tid == 0) {
            int rr = r, bin = 255;
            for (int j = 0; j < 256; j++) {
                if (rr < (int)hist[j]) { bin = j; break; }
                rr -= (int)hist[j];
            }
            bcast[0] = bin; bcast[1] = rr;
        }
        __syncthreads();
        prefix |= (uint32_t)bcast[0] << shift;
        r = bcast[1];
        done |= 0xFFu << shift;
        __syncthreads();
    }
    return fkey_inv(prefix);
}

__device__ __forceinline__ void load_group(const float4* __restrict__ xb, int g, int tid,
                                           float4* buf) {
    const int base = g * DEPTH * NT + tid;
#pragma unroll
    for (int k = 0; k < DEPTH; k++)
        buf[k] = __ldcs(&xb[base + k * NT]);
}

__device__ __forceinline__ void consume_group(
    const float4* buf, ull& s01, ull& s23, ull& q01, ull& q23,
    uint32_t& pkpos, uint32_t& pkbel, uint32_t* addr)
{
#pragma unroll
    for (int k = 0; k < DEPTH; k++) {
        float v0 = buf[k].x, v1 = buf[k].y, v2 = buf[k].z, v3 = buf[k].w;
        ull v01, v23;
        asm("mov.b64 %0, {%1, %2};" : "=l"(v01) : "f"(v0), "f"(v1));
        asm("mov.b64 %0, {%1, %2};" : "=l"(v23) : "f"(v2), "f"(v3));
        asm("add.rn.f32x2 %0, %0, %1;" : "+l"(s01) : "l"(v01));
        asm("add.rn.f32x2 %0, %0, %1;" : "+l"(s23) : "l"(v23));
        asm("fma.rn.f32x2 %0, %1, %1, %0;" : "+l"(q01) : "l"(v01));
        asm("fma.rn.f32x2 %0, %1, %1, %0;" : "+l"(q23) : "l"(v23));
        capture<0>(__float_as_int(v0), addr[0], pkbel, pkpos);
        capture<1>(__float_as_int(v1), addr[1], pkbel, pkpos);
        capture<2>(__float_as_int(v2), addr[2], pkbel, pkpos);
        capture<3>(__float_as_int(v3), addr[3], pkbel, pkpos);
    }
}

__global__ void __launch_bounds__(NT, 6) stat_kernel(
    const float* __restrict__ x, const float* __restrict__ W,
    const float* __restrict__ bias, float* __restrict__ out)
{
    extern __shared__ unsigned char smem_raw[];
    Sm* sm = reinterpret_cast<Sm*>(smem_raw);

    const int tid  = threadIdx.x;
    const int lane = tid & 31;
    const int wid  = tid >> 5;
    const int b    = blockIdx.x;

    if (tid < C_DIM) sm->fb[tid] = 0;
    if (tid == 0) sm->fball = 0;
    __syncthreads();

    const int cbase = (tid & 1) * 4;   // even tids own ch 0-3, odd own ch 4-7

    uint32_t addr[4];
#pragma unroll
    for (int j = 0; j < 4; j++)
        addr[j] = (uint32_t)__cvta_generic_to_shared(&sm->priv[tid][j][0]);

    // ---- Main streaming pass: rolled loop, peeled register double-buffer ----
    const float4* xb = reinterpret_cast<const float4*>(x + (size_t)b * T_DIM * C_DIM);
    ull s01 = 0, s23 = 0, q01 = 0, q23 = 0;
    uint32_t pkpos = 0, pkbel = 0;     // byte-packed counts (max 64 each)

    float4 A[DEPTH], Bf[DEPTH];
    load_group(xb, 0, tid, A);
#pragma unroll 2
    for (int g = 0; g < GROUPS - 2; g += 2) {
        load_group(xb, g + 1, tid, Bf);
        consume_group(A, s01, s23, q01, q23, pkpos, pkbel, addr);
        load_group(xb, g + 2, tid, A);
        consume_group(Bf, s01, s23, q01, q23, pkpos, pkbel, addr);
    }
    load_group(xb, GROUPS - 1, tid, Bf);
    consume_group(A, s01, s23, q01, q23, pkpos, pkbel, addr);
    consume_group(Bf, s01, s23, q01, q23, pkpos, pkbel, addr);

    // per-thread hit counts; any cursor past its 12 slots -> CTA-wide fallback
    {
        uint32_t pk = 0;
#pragma unroll
        for (int j = 0; j < 4; j++) {
            uint32_t base = (uint32_t)__cvta_generic_to_shared(&sm->priv[tid][j][0]);
            uint32_t hits = (addr[j] - base) >> 1;
            if (hits > SLOTS) sm->fball = 1;   // possible neighbor corruption
            pk |= (hits > 255u ? 255u : hits) << (8 * j);
        }
        sm->cntp[tid] = pk;
    }

    // unpack accumulators
    float sum[4], ssq[4];
    asm("mov.b64 {%0, %1}, %2;" : "=f"(sum[0]), "=f"(sum[1]) : "l"(s01));
    asm("mov.b64 {%0, %1}, %2;" : "=f"(sum[2]), "=f"(sum[3]) : "l"(s23));
    asm("mov.b64 {%0, %1}, %2;" : "=f"(ssq[0]), "=f"(ssq[1]) : "l"(q01));
    asm("mov.b64 {%0, %1}, %2;" : "=f"(ssq[2]), "=f"(ssq[3]) : "l"(q23));
    int cpos[4], cbel[4];
#pragma unroll
    for (int j = 0; j < 4; j++) {
        cpos[j] = (int)((pkpos >> (8 * j)) & 0xFFu);
        cbel[j] = (int)((pkbel >> (8 * j)) & 0xFFu);
    }

    // ---- parity-preserving warp reduction (masks 2..16 keep even/odd separate) ----
#pragma unroll
    for (int m = 2; m < 32; m <<= 1) {
#pragma unroll
        for (int j = 0; j < 4; j++) {
            sum[j]  += __shfl_xor_sync(0xffffffffu, sum[j], m);
            ssq[j]  += __shfl_xor_sync(0xffffffffu, ssq[j], m);
            cpos[j] += __shfl_xor_sync(0xffffffffu, cpos[j], m);
            cbel[j] += __shfl_xor_sync(0xffffffffu, cbel[j], m);
        }
    }
    if (lane < 2) {
#pragma unroll
        for (int j = 0; j < 4; j++) {
            int c = lane * 4 + j;
            sm->wpart[wid][c][0] = sum[j];
            sm->wpart[wid][c][1] = ssq[j];
            sm->wpart[wid][c][2] = (float)cpos[j];
            sm->wbelow[wid][c]   = cbel[j];
        }
    }
    __syncthreads();

    // ---- deterministic block combine ----
    if (tid < C_DIM) {
        float S = 0.f, Q = 0.f, P = 0.f; int Bl = 0;
        for (int w = 0; w < NWARPS; w++) {
            S  += sm->wpart[w][tid][0];
            Q  += sm->wpart[w][tid][1];
            P  += sm->wpart[w][tid][2];
            Bl += sm->wbelow[w][tid];
        }
        float mean = S / (float)T_DIM;
        float var  = (Q - S * S / (float)T_DIM) / (float)(T_DIM - 1);
        sm->stat[tid][1] = mean;
        sm->stat[tid][2] = P;
        sm->stat[tid][3] = sqrtf(fmaxf(var, 0.0f));
        sm->below[tid]   = Bl;
    }
    __syncthreads();

    const int fball = sm->fball;

    // ---- per-channel compaction: priv slots -> cand list (warp c owns channel c) ----
    const int c   = wid;
    const int j   = c & 3;
    const int par = c >> 2;
    int nc = 0;
    int fbc = sm->fb[c] | fball;
    if (!fbc) {
#pragma unroll 1
        for (int i = lane; i < (NT / 2) * SLOTS; i += 32) {
            int tt   = i & (NT / 2 - 1);
            int slot = i >> 7;                    // NT/2 = 128
            int tid2 = (tt << 1) | par;
            uint32_t cnt = (sm->cntp[tid2] >> (j * 8)) & 0xFFu;
            bool valid = (uint32_t)slot < cnt;    // cnt<=SLOTS when !fball
            uint16_t v = sm->priv[tid2][j][slot];
            uint32_t m = __ballot_sync(0xffffffffu, valid);
            int pos = nc + __popc(m & ((1u << lane) - 1u));
            if (valid && pos < CAP) sm->cand[c][pos] = v;
            nc += __popc(m);
        }
    }
    __syncthreads();   // priv dead from here: radix hists alias it below

    // ---- per-channel quantile: 2-pass radix select on u16 keys ----
    uint32_t* histc = reinterpret_cast<uint32_t*>(&sm->priv[0][0][0]) + c * 256;
    {
        int cb = sm->below[c];
        int l0 = RANK0 - cb;
        bool ok = !fbc && (nc <= CAP) && (l0 >= 0) && (l0 + 1 < nc);
        if (ok) {
            int k0 = warp_select16(sm->cand[c], histc, nc, l0);
            int k1 = warp_select16(sm->cand[c], histc, nc, l0 + 1);
            if (lane == 0) {
                float v0 = key_to_float(k0), v1 = key_to_float(k1);
                sm->stat[c][0] = v0 + kFrac * (v1 - v0);
            }
        } else {
            if (lane == 0) sm->fb[c] = 1;
        }
    }
    __syncthreads();

    // ---- exact fallback (block-wide; rare). reuses aliased hist region ----
    for (int cc = 0; cc < C_DIM; cc++) {
        if (sm->fb[cc] | fball) {
            uint32_t* h0 = reinterpret_cast<uint32_t*>(&sm->priv[0][0][0]);
            float v0 = block_select_global(x, b, cc, RANK0,     h0, sm->bcast);
            float v1 = block_select_global(x, b, cc, RANK0 + 1, h0, sm->bcast);
            if (tid == 0) sm->stat[cc][0] = v0 + kFrac * (v1 - v0);
            __syncthreads();
        }
    }

    // ---- tiny linear layer: feats order [q, mean, cnt, std] per channel ----
    if (tid < C_DIM) {
        float acc = sm->stat[tid][0] * __ldg(&W[tid * 4 + 0])
                  + sm->stat[tid][1] * __ldg(&W[tid * 4 + 1])
                  + sm->stat[tid][2] * __ldg(&W[tid * 4 + 2])
                  + sm->stat[tid][3] * __ldg(&W[tid * 4 + 3]);
        acc += __shfl_xor_sync(0xffu, acc, 1);
        acc += __shfl_xor_sync(0xffu, acc, 2);
        acc += __shfl_xor_sync(0xffu, acc, 4);
        if (tid == 0) out[b] = acc + __ldg(&bias[0]);
    }
}

extern "C" void kernel_launch(void* const* d_in, const int* in_sizes, int n_in,
                              void* d_out, int out_size) {
    const float* x    = (const float*)d_in[0];
    const float* W    = (const float*)d_in[1];
    const float* bias = (const float*)d_in[2];
    float* out        = (float*)d_out;
    int B = in_sizes[0] / (T_DIM * C_DIM);
    cudaFuncSetAttribute(stat_kernel, cudaFuncAttributeMaxDynamicSharedMemorySize,
                         (int)sizeof(Sm));
    stat_kernel<<<B, NT, sizeof(Sm)>>>(x, W, bias, out);
}

// round 13
// speedup vs baseline: 1.0306x; 1.0306x over previous
#include <cuda_runtime.h>
#include <cstdint>

#define T_DIM   8192
#define C_DIM   8
#define CAP     288
#define NT      256
#define NWARPS  (NT / 32)
#define DEPTH   2
#define NVEC    (T_DIM * C_DIM / 4)    // 16384 float4 per batch row
#define GROUPS  (NVEC / (NT * DEPTH))  // 32
#define RANK0   7371                   // floor(0.9 * (T_DIM-1))
#define LO_B    0x3F9AE140             // bits of ~1.21f (32-ulp aligned)
#define RANGE_BITS 0x130000            // window width in ulps (== 0x9800 keys of 32 ulp)
#define SLOTS   15                     // u16 slots per thread-channel
#define PLANE2  (NT * 4 * 2)           // 2048 B stride between u16 slot planes

typedef unsigned long long ull;

__device__ __constant__ float kFrac = (float)(0.9 * (double)(T_DIM - 1) - (double)RANK0);

struct Sm {
    uint16_t priv[SLOTS][4][NT];    // 30 KB u16 capture slots; hists alias later
    uint16_t cand[C_DIM][CAP];      // 4.5 KB compacted u16 keys
    uint32_t cntp[NT];              // packed per-thread per-channel hit counts
    float    wpart[NWARPS][C_DIM][3];
    int      wbelow[NWARPS][C_DIM];
    float    stat[C_DIM][4];
    int      below[C_DIM];
    int      fb[C_DIM];
    int      bcast[2];
};

__device__ __forceinline__ float key_to_float(int key) {
    return __int_as_float((int)LO_B + (key << 5) + 16);   // bucket midpoint, <=16 ulp err
}

__device__ __forceinline__ uint32_t fkey(float v) {
    uint32_t u = __float_as_uint(v);
    return (u & 0x80000000u) ? ~u : (u | 0x80000000u);
}
__device__ __forceinline__ float fkey_inv(uint32_t k) {
    uint32_t u = (k & 0x80000000u) ? (k ^ 0x80000000u) : ~k;
    return __uint_as_float(u);
}

// capture: if ((u32)d < RANGE_BITS && addr < maxa) { st.shared.u16 (d>>5); addr += PLANE2 }
// Cursor freezes at maxa (sacrificial guard), so hits==SLOTS flags possible loss.
__device__ __forceinline__ void capture(int d, uint32_t& addr, uint32_t maxa) {
    asm volatile(
        "{\n\t"
        ".reg .pred pw;\n\t"
        ".reg .b32 k;\n\t"
        ".reg .b16 h;\n\t"
        "setp.lt.u32 pw, %1, %2;\n\t"
        "setp.lt.and.u32 pw, %0, %3, pw;\n\t"
        "shr.u32 k, %1, 5;\n\t"
        "cvt.u16.u32 h, k;\n\t"
        "@pw st.shared.u16 [%0], h;\n\t"
        "@pw add.s32 %0, %0, %4;\n\t"
        "}"
        : "+r"(addr)
        : "r"(d), "n"(RANGE_BITS), "r"(maxa), "n"(PLANE2));
}

// sign bytes of 4 ints -> 0x01/0x00 per byte lane (PRMT sign-replicate mode)
__device__ __forceinline__ uint32_t sign4(int a0, int a1, int a2, int a3) {
    uint32_t s01, s23, sb;
    asm("prmt.b32 %0, %1, %2, 0x00FB;" : "=r"(s01) : "r"(a0), "r"(a1));
    asm("prmt.b32 %0, %1, %2, 0xFB00;" : "=r"(s23) : "r"(a2), "r"(a3));
    asm("prmt.b32 %0, %1, %2, 0x7610;" : "=r"(sb)  : "r"(s01), "r"(s23));
    return sb & 0x01010101u;
}

// Exact rank-r select over n u16 keys; one warp, 2-pass byte radix.
__device__ int warp_select16(const uint16_t* cand, uint32_t* hist, int n, int r) {
    const int lane = threadIdx.x & 31;
    int hibin = -1;
    for (int pass = 0; pass < 2; pass++) {
        for (int i = lane; i < 256; i += 32) hist[i] = 0;
        __syncwarp();
        for (int i = lane; i < n; i += 32) {
            uint32_t k = cand[i];
            if (pass == 0) atomicAdd(&hist[k >> 8], 1u);
            else if ((int)(k >> 8) == hibin) atomicAdd(&hist[k & 255u], 1u);
        }
        __syncwarp();
        uint32_t bv[8];
        uint32_t loc = 0;
#pragma unroll
        for (int j = 0; j < 8; j++) { bv[j] = hist[lane * 8 + j]; loc += bv[j]; }
        uint32_t pre = loc;
#pragma unroll
        for (int d = 1; d < 32; d <<= 1) {
            uint32_t t = __shfl_up_sync(0xffffffffu, pre, d);
            if (lane >= d) pre += t;
        }
        int excl = (int)(pre - loc);
        bool myfind = (r >= excl) && (r < excl + (int)loc);
        uint32_t ball = __ballot_sync(0xffffffffu, myfind);
        int src = __ffs(ball) - 1;
        int bin_out = 0, rem_out = 0;
        if (myfind) {
            int rem = r - excl, bsel = 0;
            bool found = false;
#pragma unroll
            for (int j = 0; j < 8; j++) {
                if (!found) {
                    if (rem < (int)bv[j]) { bsel = j; found = true; }
                    else rem -= (int)bv[j];
                }
            }
            bin_out = lane * 8 + bsel;
            rem_out = rem;
        }
        int bin = __shfl_sync(0xffffffffu, bin_out, src);
        r       = __shfl_sync(0xffffffffu, rem_out, src);
        if (pass == 0) hibin = bin;
        else           hibin = (hibin << 8) | bin;
        __syncwarp();
    }
    return hibin;   // full 16-bit key
}

// Block-wide exact rank-r selection from global (fallback; rare).
__device__ float block_select_global(const float* __restrict__ x, int b, int c, int r,
                                     uint32_t* hist, int* bcast) {
    const int tid = threadIdx.x;
    uint32_t prefix = 0, done = 0;
    for (int shift = 24; shift >= 0; shift -= 8) {
        for (int i = tid; i < 256; i += NT) hist[i] = 0;
        __syncthreads();
        for (int t = tid; t < T_DIM; t += NT) {
            float v = x[((size_t)b * T_DIM + t) * C_DIM + c];
            uint32_t k = fkey(v);
            if ((k & done) == prefix) atomicAdd(&hist[(k >> shift) & 255u], 1u);
        }
        __syncthreads();
        if (tid == 0) {
            int rr = r, bin = 255;
            for (int j = 0; j < 256; j++) {
                if (rr < (int)hist[j]) { bin = j; break; }
                rr -= (int)hist[j];
            }
            bcast[0] = bin; bcast[1] = rr;
        }
        __syncthreads();
        prefix |= (uint32_t)bcast[0] << shift;
        r = bcast[1];
        done |= 0xFFu << shift;
        __syncthreads();
    }
    return fkey_inv(prefix);
}

__device__ __forceinline__ void load_group(const float4* __restrict__ xb, int g, int tid,
                                           float4* buf) {
    const int base = g * DEPTH * NT + tid;
#pragma unroll
    for (int k = 0; k < DEPTH; k++)
        buf[k] = __ldcs(&xb[base + k * NT]);
}

__device__ __forceinline__ void consume_group(
    const float4* buf, ull& s01, ull& s23, ull& q01, ull& q23,
    uint32_t& pkneg, uint32_t& pkbel, uint32_t* addr, const uint32_t* maxa)
{
#pragma unroll
    for (int k = 0; k < DEPTH; k++) {
        float v0 = buf[k].x, v1 = buf[k].y, v2 = buf[k].z, v3 = buf[k].w;
        ull v01, v23;
        asm("mov.b64 %0, {%1, %2};" : "=l"(v01) : "f"(v0), "f"(v1));
        asm("mov.b64 %0, {%1, %2};" : "=l"(v23) : "f"(v2), "f"(v3));
        asm("add.rn.f32x2 %0, %0, %1;" : "+l"(s01) : "l"(v01));
        asm("add.rn.f32x2 %0, %0, %1;" : "+l"(s23) : "l"(v23));
        asm("fma.rn.f32x2 %0, %1, %1, %0;" : "+l"(q01) : "l"(v01));
        asm("fma.rn.f32x2 %0, %1, %1, %0;" : "+l"(q23) : "l"(v23));
        int b0 = __float_as_int(v0), b1 = __float_as_int(v1);
        int b2 = __float_as_int(v2), b3 = __float_as_int(v3);
        int d0 = b0 - (int)LO_B, d1 = b1 - (int)LO_B;
        int d2 = b2 - (int)LO_B, d3 = b3 - (int)LO_B;
        capture(d0, addr[0], maxa[0]);
        capture(d1, addr[1], maxa[1]);
        capture(d2, addr[2], maxa[2]);
        capture(d3, addr[3], maxa[3]);
        pkbel += sign4(d0, d1, d2, d3);   // exact: d<0 <=> x < LO
        pkneg += sign4(b0, b1, b2, b3);   // sign(x); cpos = 64 - neg per channel
    }
}

__global__ void __launch_bounds__(NT, 5) stat_kernel(
    const float* __restrict__ x, const float* __restrict__ W,
    const float* __restrict__ bias, float* __restrict__ out)
{
    extern __shared__ unsigned char smem_raw[];
    Sm* sm = reinterpret_cast<Sm*>(smem_raw);

    const int tid  = threadIdx.x;
    const int lane = tid & 31;
    const int wid  = tid >> 5;
    const int b    = blockIdx.x;

    if (tid < C_DIM) sm->fb[tid] = 0;
    __syncthreads();

    const int cbase = (tid & 1) * 4;   // even tids own ch 0-3, odd own ch 4-7

    uint32_t addr[4], maxa[4];
#pragma unroll
    for (int j = 0; j < 4; j++) {
        addr[j] = (uint32_t)__cvta_generic_to_shared(&sm->priv[0][j][tid]);
        maxa[j] = addr[j] + SLOTS * PLANE2;    // stores blocked at addr==maxa
    }

    // ---- Main streaming pass: rolled loop, peeled register double-buffer ----
    const float4* xb = reinterpret_cast<const float4*>(x + (size_t)b * T_DIM * C_DIM);
    ull s01 = 0, s23 = 0, q01 = 0, q23 = 0;
    uint32_t pkneg = 0, pkbel = 0;     // byte-packed counts (max 64 each)

    float4 A[DEPTH], Bf[DEPTH];
    load_group(xb, 0, tid, A);
#pragma unroll 1
    for (int g = 0; g < GROUPS - 2; g += 2) {
        load_group(xb, g + 1, tid, Bf);
        consume_group(A, s01, s23, q01, q23, pkneg, pkbel, addr, maxa);
        load_group(xb, g + 2, tid, A);
        consume_group(Bf, s01, s23, q01, q23, pkneg, pkbel, addr, maxa);
    }
    load_group(xb, GROUPS - 1, tid, Bf);
    consume_group(A, s01, s23, q01, q23, pkneg, pkbel, addr, maxa);
    consume_group(Bf, s01, s23, q01, q23, pkneg, pkbel, addr, maxa);

    // per-thread hit counts; cursor saturation (hits>=SLOTS) -> possible loss -> fallback
    {
        uint32_t pk = 0;
#pragma unroll
        for (int j = 0; j < 4; j++) {
            uint32_t hits = (addr[j] - (maxa[j] - SLOTS * PLANE2)) >> 11;  // PLANE2=2048
            if (hits >= SLOTS) sm->fb[cbase + j] = 1;
            pk |= hits << (8 * j);
        }
        sm->cntp[tid] = pk;
    }

    // unpack accumulators
    float sum[4], ssq[4];
    asm("mov.b64 {%0, %1}, %2;" : "=f"(sum[0]), "=f"(sum[1]) : "l"(s01));
    asm("mov.b64 {%0, %1}, %2;" : "=f"(sum[2]), "=f"(sum[3]) : "l"(s23));
    asm("mov.b64 {%0, %1}, %2;" : "=f"(ssq[0]), "=f"(ssq[1]) : "l"(q01));
    asm("mov.b64 {%0, %1}, %2;" : "=f"(ssq[2]), "=f"(ssq[3]) : "l"(q23));
    int cpos[4], cbel[4];
#pragma unroll
    for (int j = 0; j < 4; j++) {
        cpos[j] = 64 - (int)((pkneg >> (8 * j)) & 0xFFu);   // 64 elems per channel
        cbel[j] = (int)((pkbel >> (8 * j)) & 0xFFu);
    }

    // ---- parity-preserving warp reduction (masks 2..16 keep even/odd separate) ----
#pragma unroll
    for (int m = 2; m < 32; m <<= 1) {
#pragma unroll
        for (int j = 0; j < 4; j++) {
            sum[j]  += __shfl_xor_sync(0xffffffffu, sum[j], m);
            ssq[j]  += __shfl_xor_sync(0xffffffffu, ssq[j], m);
            cpos[j] += __shfl_xor_sync(0xffffffffu, cpos[j], m);
            cbel[j] += __shfl_xor_sync(0xffffffffu, cbel[j], m);
        }
    }
    if (lane < 2) {
#pragma unroll
        for (int j = 0; j < 4; j++) {
            int c = lane * 4 + j;
            sm->wpart[wid][c][0] = sum[j];
            sm->wpart[wid][c][1] = ssq[j];
            sm->wpart[wid][c][2] = (float)cpos[j];
            sm->wbelow[wid][c]   = cbel[j];
        }
    }
    __syncthreads();

    // ---- deterministic block combine ----
    if (tid < C_DIM) {
        float S = 0.f, Q = 0.f, P = 0.f; int Bl = 0;
        for (int w = 0; w < NWARPS; w++) {
            S  += sm->wpart[w][tid][0];
            Q  += sm->wpart[w][tid][1];
            P  += sm->wpart[w][tid][2];
            Bl += sm->wbelow[w][tid];
        }
        float mean = S / (float)T_DIM;
        float var  = (Q - S * S / (float)T_DIM) / (float)(T_DIM - 1);
        sm->stat[tid][1] = mean;
        sm->stat[tid][2] = P;
        sm->stat[tid][3] = sqrtf(fmaxf(var, 0.0f));
        sm->below[tid]   = Bl;
    }
    __syncthreads();

    // ---- per-channel compaction: priv slots -> cand list (warp c owns channel c) ----
    const int c   = wid;
    const int j   = c & 3;
    const int par = c >> 2;
    int nc = 0;
    int fbc = sm->fb[c];
    if (!fbc) {
#pragma unroll 1
        for (int i = lane; i < (NT / 2) * SLOTS; i += 32) {
            int tt   = i & (NT / 2 - 1);
            int slot = i >> 7;                    // NT/2 = 128
            int tid2 = (tt << 1) | par;
            uint32_t cnt = (sm->cntp[tid2] >> (j * 8)) & 0xFFu;
            bool valid = (uint32_t)slot < cnt;
            uint16_t v = sm->priv[slot][j][tid2];
            uint32_t m = __ballot_sync(0xffffffffu, valid);
            int pos = nc + __popc(m & ((1u << lane) - 1u));
            if (valid && pos < CAP) sm->cand[c][pos] = v;
            nc += __popc(m);
        }
    }
    __syncthreads();   // priv dead from here: radix hists alias it below

    // ---- per-channel quantile: 2-pass radix select on u16 keys ----
    uint32_t* histc = reinterpret_cast<uint32_t*>(&sm->priv[0][0][0]) + c * 256;
    {
        int cb = sm->below[c];
        int l0 = RANK0 - cb;
        bool ok = !fbc && (nc <= CAP) && (l0 >= 0) && (l0 + 1 < nc);
        if (ok) {
            int k0 = warp_select16(sm->cand[c], histc, nc, l0);
            int k1 = warp_select16(sm->cand[c], histc, nc, l0 + 1);
            if (lane == 0) {
                float v0 = key_to_float(k0), v1 = key_to_float(k1);
                sm->stat[c][0] = v0 + kFrac * (v1 - v0);
            }
        } else {
            if (lane == 0) sm->fb[c] = 1;
        }
    }
    __syncthreads();

    // ---- exact fallback (block-wide; rare). reuses aliased hist region ----
    for (int cc = 0; cc < C_DIM; cc++) {
        if (sm->fb[cc]) {
            uint32_t* h0 = reinterpret_cast<uint32_t*>(&sm->priv[0][0][0]);
            float v0 = block_select_global(x, b, cc, RANK0,     h0, sm->bcast);
            float v1 = block_select_global(x, b, cc, RANK0 + 1, h0, sm->bcast);
            if (tid == 0) sm->stat[cc][0] = v0 + kFrac * (v1 - v0);
            __syncthreads();
        }
    }

    // ---- tiny linear layer: feats order [q, mean, cnt, std] per channel ----
    if (tid < C_DIM) {
        float acc = sm->stat[tid][0] * __ldg(&W[tid * 4 + 0])
                  + sm->stat[tid][1] * __ldg(&W[tid * 4 + 1])
                  + sm->stat[tid][2] * __ldg(&W[tid * 4 + 2])
                  + sm->stat[tid][3] * __ldg(&W[tid * 4 + 3]);
        acc += __shfl_xor_sync(0xffu, acc, 1);
        acc += __shfl_xor_sync(0xffu, acc, 2);
        acc += __shfl_xor_sync(0xffu, acc, 4);
        if (tid == 0) out[b] = acc + __ldg(&bias[0]);
    }
}

extern "C" void kernel_launch(void* const* d_in, const int* in_sizes, int n_in,
                              void* d_out, int out_size) {
    const float* x    = (const float*)d_in[0];
    const float* W    = (const float*)d_in[1];
    const float* bias = (const float*)d_in[2];
    float* out        = (float*)d_out;
    int B = in_sizes[0] / (T_DIM * C_DIM);
    cudaFuncSetAttribute(stat_kernel, cudaFuncAttributeMaxDynamicSharedMemorySize,
                         (int)sizeof(Sm));
    stat_kernel<<<B, NT, sizeof(Sm)>>>(x, W, bias, out);
}

// round 14
// speedup vs baseline: 38.7224x; 37.5734x over previous
#include <cuda_runtime.h>
#include <cstdint>

#define T_DIM   8192
#define C_DIM   8
#define CAP     288
#define NT      256
#define NWARPS  (NT / 32)
#define DEPTH   2
#define NVEC    (T_DIM * C_DIM / 4)    // 16384 float4 per batch row
#define GROUPS  (NVEC / (NT * DEPTH))  // 32
#define RANK0   7371                   // floor(0.9 * (T_DIM-1))
#define LO_B    0x3F9AE140             // bits of ~1.21f (32-ulp aligned)
#define LO_S    (LO_B >> 5)
#define RANGE_S 0x9800                 // 38912 buckets of 32 ulps -> HI = ~1.3506f
#define SLOTS   15                     // u16 slots per thread-channel
#define PLANE2  (NT * 4 * 2)           // 2048 B stride between u16 slot planes

typedef unsigned long long ull;

__device__ __constant__ float kFrac = (float)(0.9 * (double)(T_DIM - 1) - (double)RANK0);

struct Sm {
    uint16_t priv[SLOTS][4][NT];    // 30 KB u16 capture slots; hists alias later
    uint16_t cand[C_DIM][CAP];      // 4.5 KB compacted u16 keys
    uint32_t cntp[NT];              // packed per-thread per-channel hit counts
    float    wpart[NWARPS][C_DIM][3];
    int      wbelow[NWARPS][C_DIM];
    float    stat[C_DIM][4];
    int      below[C_DIM];
    int      fb[C_DIM];
    int      bcast[2];
};

__device__ __forceinline__ float key_to_float(int key) {
    return __int_as_float((int)LO_B + (key << 5) + 16);   // bucket midpoint, <=16 ulp err
}

__device__ __forceinline__ uint32_t fkey(float v) {
    uint32_t u = __float_as_uint(v);
    return (u & 0x80000000u) ? ~u : (u | 0x80000000u);
}
__device__ __forceinline__ float fkey_inv(uint32_t k) {
    uint32_t u = (k & 0x80000000u) ? (k ^ 0x80000000u) : ~k;
    return __uint_as_float(u);
}

// fused hot path, compile-time channel J (R10-proven, shift-first => overflow-safe):
//   key = (vb>>5) - LO_S          (range +/-2^26, never overflows)
//   pkbel += (key<0)<<8J
//   if (0<=key<RANGE_S && addr<maxa) { st.shared.u16 key; addr += PLANE2 }
template <int J>
__device__ __forceinline__ void capture(int vb, uint32_t& addr, uint32_t maxa,
                                        uint32_t& pkbel) {
    asm volatile(
        "{\n\t"
        ".reg .pred plo, pw;\n\t"
        ".reg .b32 ks, key;\n\t"
        ".reg .b16 h;\n\t"
        "shr.s32 ks, %2, 5;\n\t"
        "sub.s32 key, ks, %3;\n\t"
        "setp.lt.s32 plo, key, 0;\n\t"
        "setp.lt.u32 pw, key, %4;\n\t"
        "setp.lt.and.u32 pw, %0, %5, pw;\n\t"
        "@plo add.s32 %1, %1, %6;\n\t"
        "cvt.u16.u32 h, key;\n\t"
        "@pw st.shared.u16 [%0], h;\n\t"
        "@pw add.s32 %0, %0, %7;\n\t"
        "}"
        : "+r"(addr), "+r"(pkbel)
        : "r"(vb), "n"(LO_S), "n"(RANGE_S), "r"(maxa),
          "n"(1 << (8 * J)), "n"(PLANE2));
}

// sign bytes of 4 ints -> 0x01/0x00 per byte lane (PRMT sign-replicate; no arithmetic)
__device__ __forceinline__ uint32_t sign4(int a0, int a1, int a2, int a3) {
    uint32_t s01, s23, sb;
    asm("prmt.b32 %0, %1, %2, 0x00FB;" : "=r"(s01) : "r"(a0), "r"(a1));
    asm("prmt.b32 %0, %1, %2, 0xFB00;" : "=r"(s23) : "r"(a2), "r"(a3));
    asm("prmt.b32 %0, %1, %2, 0x7610;" : "=r"(sb)  : "r"(s01), "r"(s23));
    return sb & 0x01010101u;
}

// Exact rank-r select over n u16 keys; one warp, 2-pass byte radix.
__device__ int warp_select16(const uint16_t* cand, uint32_t* hist, int n, int r) {
    const int lane = threadIdx.x & 31;
    int hibin = -1;
    for (int pass = 0; pass < 2; pass++) {
        for (int i = lane; i < 256; i += 32) hist[i] = 0;
        __syncwarp();
        for (int i = lane; i < n; i += 32) {
            uint32_t k = cand[i];
            if (pass == 0) atomicAdd(&hist[k >> 8], 1u);
            else if ((int)(k >> 8) == hibin) atomicAdd(&hist[k & 255u], 1u);
        }
        __syncwarp();
        uint32_t bv[8];
        uint32_t loc = 0;
#pragma unroll
        for (int j = 0; j < 8; j++) { bv[j] = hist[lane * 8 + j]; loc += bv[j]; }
        uint32_t pre = loc;
#pragma unroll
        for (int d = 1; d < 32; d <<= 1) {
            uint32_t t = __shfl_up_sync(0xffffffffu, pre, d);
            if (lane >= d) pre += t;
        }
        int excl = (int)(pre - loc);
        bool myfind = (r >= excl) && (r < excl + (int)loc);
        uint32_t ball = __ballot_sync(0xffffffffu, myfind);
        int src = __ffs(ball) - 1;
        int bin_out = 0, rem_out = 0;
        if (myfind) {
            int rem = r - excl, bsel = 0;
            bool found = false;
#pragma unroll
            for (int j = 0; j < 8; j++) {
                if (!found) {
                    if (rem < (int)bv[j]) { bsel = j; found = true; }
                    else rem -= (int)bv[j];
                }
            }
            bin_out = lane * 8 + bsel;
            rem_out = rem;
        }
        int bin = __shfl_sync(0xffffffffu, bin_out, src);
        r       = __shfl_sync(0xffffffffu, rem_out, src);
        if (pass == 0) hibin = bin;
        else           hibin = (hibin << 8) | bin;
        __syncwarp();
    }
    return hibin;   // full 16-bit key
}

// Block-wide exact rank-r selection from global (fallback; rare).
__device__ float block_select_global(const float* __restrict__ x, int b, int c, int r,
                                     uint32_t* hist, int* bcast) {
    const int tid = threadIdx.x;
    uint32_t prefix = 0, done = 0;
    for (int shift = 24; shift >= 0; shift -= 8) {
        for (int i = tid; i < 256; i += NT) hist[i] = 0;
        __syncthreads();
        for (int t = tid; t < T_DIM; t += NT) {
            float v = x[((size_t)b * T_DIM + t) * C_DIM + c];
            uint32_t k = fkey(v);
            if ((k & done) == prefix) atomicAdd(&hist[(k >> shift) & 255u], 1u);
        }
        __syncthreads();
        if (tid == 0) {
            int rr = r, bin = 255;
            for (int j = 0; j < 256; j++) {
                if (rr < (int)hist[j]) { bin = j; break; }
                rr -= (int)hist[j];
            }
            bcast[0] = bin; bcast[1] = rr;
        }
        __syncthreads();
        prefix |= (uint32_t)bcast[0] << shift;
        r = bcast[1];
        done |= 0xFFu << shift;
        __syncthreads();
    }
    return fkey_inv(prefix);
}

__device__ __forceinline__ void load_group(const float4* __restrict__ xb, int g, int tid,
                                           float4* buf) {
    const int base = g * DEPTH * NT + tid;
#pragma unroll
    for (int k = 0; k < DEPTH; k++)
        buf[k] = __ldcs(&xb[base + k * NT]);
}

__device__ __forceinline__ void consume_group(
    const float4* buf, ull& s01, ull& s23, ull& q01, ull& q23,
    uint32_t& pkneg, uint32_t& pkbel, uint32_t* addr, const uint32_t* maxa)
{
#pragma unroll
    for (int k = 0; k < DEPTH; k++) {
        float v0 = buf[k].x, v1 = buf[k].y, v2 = buf[k].z, v3 = buf[k].w;
        ull v01, v23;
        asm("mov.b64 %0, {%1, %2};" : "=l"(v01) : "f"(v0), "f"(v1));
        asm("mov.b64 %0, {%1, %2};" : "=l"(v23) : "f"(v2), "f"(v3));
        asm("add.rn.f32x2 %0, %0, %1;" : "+l"(s01) : "l"(v01));
        asm("add.rn.f32x2 %0, %0, %1;" : "+l"(s23) : "l"(v23));
        asm("fma.rn.f32x2 %0, %1, %1, %0;" : "+l"(q01) : "l"(v01));
        asm("fma.rn.f32x2 %0, %1, %1, %0;" : "+l"(q23) : "l"(v23));
        int b0 = __float_as_int(v0), b1 = __float_as_int(v1);
        int b2 = __float_as_int(v2), b3 = __float_as_int(v3);
        capture<0>(b0, addr[0], maxa[0], pkbel);
        capture<1>(b1, addr[1], maxa[1], pkbel);
        capture<2>(b2, addr[2], maxa[2], pkbel);
        capture<3>(b3, addr[3], maxa[3], pkbel);
        pkneg += sign4(b0, b1, b2, b3);   // sign(x); cpos = 64 - neg per channel
    }
}

__global__ void __launch_bounds__(NT, 5) stat_kernel(
    const float* __restrict__ x, const float* __restrict__ W,
    const float* __restrict__ bias, float* __restrict__ out)
{
    extern __shared__ unsigned char smem_raw[];
    Sm* sm = reinterpret_cast<Sm*>(smem_raw);

    const int tid  = threadIdx.x;
    const int lane = tid & 31;
    const int wid  = tid >> 5;
    const int b    = blockIdx.x;

    if (tid < C_DIM) sm->fb[tid] = 0;
    __syncthreads();

    const int cbase = (tid & 1) * 4;   // even tids own ch 0-3, odd own ch 4-7

    uint32_t addr[4], maxa[4];
#pragma unroll
    for (int j = 0; j < 4; j++) {
        addr[j] = (uint32_t)__cvta_generic_to_shared(&sm->priv[0][j][tid]);
        maxa[j] = addr[j] + SLOTS * PLANE2;    // stores blocked at addr==maxa
    }

    // ---- Main streaming pass: rolled loop, peeled register double-buffer ----
    const float4* xb = reinterpret_cast<const float4*>(x + (size_t)b * T_DIM * C_DIM);
    ull s01 = 0, s23 = 0, q01 = 0, q23 = 0;
    uint32_t pkneg = 0, pkbel = 0;     // byte-packed counts (max 64 each)

    float4 A[DEPTH], Bf[DEPTH];
    load_group(xb, 0, tid, A);
#pragma unroll 1
    for (int g = 0; g < GROUPS - 2; g += 2) {
        load_group(xb, g + 1, tid, Bf);
        consume_group(A, s01, s23, q01, q23, pkneg, pkbel, addr, maxa);
        load_group(xb, g + 2, tid, A);
        consume_group(Bf, s01, s23, q01, q23, pkneg, pkbel, addr, maxa);
    }
    load_group(xb, GROUPS - 1, tid, Bf);
    consume_group(A, s01, s23, q01, q23, pkneg, pkbel, addr, maxa);
    consume_group(Bf, s01, s23, q01, q23, pkneg, pkbel, addr, maxa);

    // per-thread hit counts; cursor saturation (hits>=SLOTS) -> possible loss -> fallback
    {
        uint32_t pk = 0;
#pragma unroll
        for (int j = 0; j < 4; j++) {
            uint32_t hits = (addr[j] - (maxa[j] - SLOTS * PLANE2)) >> 11;  // PLANE2=2048
            if (hits >= SLOTS) sm->fb[cbase + j] = 1;
            pk |= hits << (8 * j);
        }
        sm->cntp[tid] = pk;
    }

    // unpack accumulators
    float sum[4], ssq[4];
    asm("mov.b64 {%0, %1}, %2;" : "=f"(sum[0]), "=f"(sum[1]) : "l"(s01));
    asm("mov.b64 {%0, %1}, %2;" : "=f"(sum[2]), "=f"(sum[3]) : "l"(s23));
    asm("mov.b64 {%0, %1}, %2;" : "=f"(ssq[0]), "=f"(ssq[1]) : "l"(q01));
    asm("mov.b64 {%0, %1}, %2;" : "=f"(ssq[2]), "=f"(ssq[3]) : "l"(q23));
    int cpos[4], cbel[4];
#pragma unroll
    for (int j = 0; j < 4; j++) {
        cpos[j] = 64 - (int)((pkneg >> (8 * j)) & 0xFFu);   // 64 elems per channel
        cbel[j] = (int)((pkbel >> (8 * j)) & 0xFFu);
    }

    // ---- parity-preserving warp reduction (masks 2..16 keep even/odd separate) ----
#pragma unroll
    for (int m = 2; m < 32; m <<= 1) {
#pragma unroll
        for (int j = 0; j < 4; j++) {
            sum[j]  += __shfl_xor_sync(0xffffffffu, sum[j], m);
            ssq[j]  += __shfl_xor_sync(0xffffffffu, ssq[j], m);
            cpos[j] += __shfl_xor_sync(0xffffffffu, cpos[j], m);
            cbel[j] += __shfl_xor_sync(0xffffffffu, cbel[j], m);
        }
    }
    if (lane < 2) {
#pragma unroll
        for (int j = 0; j < 4; j++) {
            int c = lane * 4 + j;
            sm->wpart[wid][c][0] = sum[j];
            sm->wpart[wid][c][1] = ssq[j];
            sm->wpart[wid][c][2] = (float)cpos[j];
            sm->wbelow[wid][c]   = cbel[j];
        }
    }
    __syncthreads();

    // ---- deterministic block combine ----
    if (tid < C_DIM) {
        float S = 0.f, Q = 0.f, P = 0.f; int Bl = 0;
        for (int w = 0; w < NWARPS; w++) {
            S  += sm->wpart[w][tid][0];
            Q  += sm->wpart[w][tid][1];
            P  += sm->wpart[w][tid][2];
            Bl += sm->wbelow[w][tid];
        }
        float mean = S / (float)T_DIM;
        float var  = (Q - S * S / (float)T_DIM) / (float)(T_DIM - 1);
        sm->stat[tid][1] = mean;
        sm->stat[tid][2] = P;
        sm->stat[tid][3] = sqrtf(fmaxf(var, 0.0f));
        sm->below[tid]   = Bl;
    }
    __syncthreads();

    // ---- per-channel compaction: priv slots -> cand list (warp c owns channel c) ----
    const int c   = wid;
    const int j   = c & 3;
    const int par = c >> 2;
    int nc = 0;
    int fbc = sm->fb[c];
    if (!fbc) {
#pragma unroll 1
        for (int i = lane; i < (NT / 2) * SLOTS; i += 32) {
            int tt   = i & (NT / 2 - 1);
            int slot = i >> 7;                    // NT/2 = 128
            int tid2 = (tt << 1) | par;
            uint32_t cnt = (sm->cntp[tid2] >> (j * 8)) & 0xFFu;
            bool valid = (uint32_t)slot < cnt;
            uint16_t v = sm->priv[slot][j][tid2];
            uint32_t m = __ballot_sync(0xffffffffu, valid);
            int pos = nc + __popc(m & ((1u << lane) - 1u));
            if (valid && pos < CAP) sm->cand[c][pos] = v;
            nc += __popc(m);
        }
    }
    __syncthreads();   // priv dead from here: radix hists alias it below

    // ---- per-channel quantile: 2-pass radix select on u16 keys ----
    uint32_t* histc = reinterpret_cast<uint32_t*>(&sm->priv[0][0][0]) + c * 256;
    {
        int cb = sm->below[c];
        int l0 = RANK0 - cb;
        bool ok = !fbc && (nc <= CAP) && (l0 >= 0) && (l0 + 1 < nc);
        if (ok) {
            int k0 = warp_select16(sm->cand[c], histc, nc, l0);
            int k1 = warp_select16(sm->cand[c], histc, nc, l0 + 1);
            if (lane == 0) {
                float v0 = key_to_float(k0), v1 = key_to_float(k1);
                sm->stat[c][0] = v0 + kFrac * (v1 - v0);
            }
        } else {
            if (lane == 0) sm->fb[c] = 1;
        }
    }
    __syncthreads();

    // ---- exact fallback (block-wide; rare). reuses aliased hist region ----
    for (int cc = 0; cc < C_DIM; cc++) {
        if (sm->fb[cc]) {
            uint32_t* h0 = reinterpret_cast<uint32_t*>(&sm->priv[0][0][0]);
            float v0 = block_select_global(x, b, cc, RANK0,     h0, sm->bcast);
            float v1 = block_select_global(x, b, cc, RANK0 + 1, h0, sm->bcast);
            if (tid == 0) sm->stat[cc][0] = v0 + kFrac * (v1 - v0);
            __syncthreads();
        }
    }

    // ---- tiny linear layer: feats order [q, mean, cnt, std] per channel ----
    if (tid < C_DIM) {
        float acc = sm->stat[tid][0] * __ldg(&W[tid * 4 + 0])
                  + sm->stat[tid][1] * __ldg(&W[tid * 4 + 1])
                  + sm->stat[tid][2] * __ldg(&W[tid * 4 + 2])
                  + sm->stat[tid][3] * __ldg(&W[tid * 4 + 3]);
        acc += __shfl_xor_sync(0xffu, acc, 1);
        acc += __shfl_xor_sync(0xffu, acc, 2);
        acc += __shfl_xor_sync(0xffu, acc, 4);
        if (tid == 0) out[b] = acc + __ldg(&bias[0]);
    }
}

extern "C" void kernel_launch(void* const* d_in, const int* in_sizes, int n_in,
                              void* d_out, int out_size) {
    const float* x    = (const float*)d_in[0];
    const float* W    = (const float*)d_in[1];
    const float* bias = (const float*)d_in[2];
    float* out        = (float*)d_out;
    int B = in_sizes[0] / (T_DIM * C_DIM);
    cudaFuncSetAttribute(stat_kernel, cudaFuncAttributeMaxDynamicSharedMemorySize,
                         (int)sizeof(Sm));
    stat_kernel<<<B, NT, sizeof(Sm)>>>(x, W, bias, out);
}

// round 15
// speedup vs baseline: 38.9649x; 1.0063x over previous
#include <cuda_runtime.h>
#include <cstdint>

#define T_DIM   8192
#define C_DIM   8
#define CAP     288
#define NT      256
#define NWARPS  (NT / 32)
#define DEPTH   2
#define NVEC    (T_DIM * C_DIM / 4)    // 16384 float4 per batch row
#define GROUPS  (NVEC / (NT * DEPTH))  // 32
#define RANK0   7371                   // floor(0.9 * (T_DIM-1))
#define LO_B    0x3F9AE140             // bits of ~1.21f (32-ulp aligned)
#define LO_S    (LO_B >> 5)
#define RANGE_S 0x9800                 // 38912 buckets of 32 ulps -> HI = ~1.3506f
#define SLOTS   15                     // u16 slots per thread-channel
#define PLANE2  (NT * 4 * 2)           // 2048 B stride between u16 slot planes

typedef unsigned long long ull;

__device__ __constant__ float kFrac = (float)(0.9 * (double)(T_DIM - 1) - (double)RANK0);

struct Sm {
    uint16_t priv[SLOTS][4][NT];    // 30 KB u16 capture slots; hists alias later
    uint16_t cand[C_DIM][CAP];      // 4.5 KB compacted u16 keys
    uint32_t cntp[NT];              // packed per-thread per-channel hit counts
    float    wpart[NWARPS][C_DIM][3];
    int      wbelow[NWARPS][C_DIM];
    float    stat[C_DIM][4];
    int      below[C_DIM];
    int      fb[C_DIM];
    int      bcast[2];
};

__device__ __forceinline__ float key_to_float(int key) {
    return __int_as_float((int)LO_B + (key << 5) + 16);   // bucket midpoint, <=16 ulp err
}

__device__ __forceinline__ uint32_t fkey(float v) {
    uint32_t u = __float_as_uint(v);
    return (u & 0x80000000u) ? ~u : (u | 0x80000000u);
}
__device__ __forceinline__ float fkey_inv(uint32_t k) {
    uint32_t u = (k & 0x80000000u) ? (k ^ 0x80000000u) : ~k;
    return __uint_as_float(u);
}

// sign bytes of 4 ints -> 0x01/0x00 per byte lane (PRMT sign-replicate; no arithmetic)
__device__ __forceinline__ uint32_t sign4(int a0, int a1, int a2, int a3) {
    uint32_t s01, s23, sb;
    asm("prmt.b32 %0, %1, %2, 0x00FB;" : "=r"(s01) : "r"(a0), "r"(a1));
    asm("prmt.b32 %0, %1, %2, 0xFB00;" : "=r"(s23) : "r"(a2), "r"(a3));
    asm("prmt.b32 %0, %1, %2, 0x7610;" : "=r"(sb)  : "r"(s01), "r"(s23));
    return sb & 0x01010101u;
}

// merged window capture for 4 channels: for each j,
//   if (0 <= key_j < RANGE_S && addr_j < maxa_j) { st.shared.u16 key_j; addr_j += PLANE2 }
// keys are shift-first ((vb>>5)-LO_S): overflow-safe, so unsigned test covers both bounds.
__device__ __forceinline__ void capture4(int k0, int k1, int k2, int k3,
                                         uint32_t& a0, uint32_t& a1,
                                         uint32_t& a2, uint32_t& a3,
                                         uint32_t m0, uint32_t m1,
                                         uint32_t m2, uint32_t m3) {
    asm volatile(
        "{\n\t"
        ".reg .pred p0, p1, p2, p3;\n\t"
        ".reg .b16 h0, h1, h2, h3;\n\t"
        "setp.lt.u32 p0, %4, %12;\n\t"
        "setp.lt.and.u32 p0, %0, %8, p0;\n\t"
        "cvt.u16.u32 h0, %4;\n\t"
        "@p0 st.shared.u16 [%0], h0;\n\t"
        "@p0 add.s32 %0, %0, %13;\n\t"
        "setp.lt.u32 p1, %5, %12;\n\t"
        "setp.lt.and.u32 p1, %1, %9, p1;\n\t"
        "cvt.u16.u32 h1, %5;\n\t"
        "@p1 st.shared.u16 [%1], h1;\n\t"
        "@p1 add.s32 %1, %1, %13;\n\t"
        "setp.lt.u32 p2, %6, %12;\n\t"
        "setp.lt.and.u32 p2, %2, %10, p2;\n\t"
        "cvt.u16.u32 h2, %6;\n\t"
        "@p2 st.shared.u16 [%2], h2;\n\t"
        "@p2 add.s32 %2, %2, %13;\n\t"
        "setp.lt.u32 p3, %7, %12;\n\t"
        "setp.lt.and.u32 p3, %3, %11, p3;\n\t"
        "cvt.u16.u32 h3, %7;\n\t"
        "@p3 st.shared.u16 [%3], h3;\n\t"
        "@p3 add.s32 %3, %3, %13;\n\t"
        "}"
        : "+r"(a0), "+r"(a1), "+r"(a2), "+r"(a3)
        : "r"(k0), "r"(k1), "r"(k2), "r"(k3),
          "r"(m0), "r"(m1), "r"(m2), "r"(m3),
          "n"(RANGE_S), "n"(PLANE2));
}

// Exact rank-r select over n u16 keys; one warp, 2-pass byte radix.
__device__ int warp_select16(const uint16_t* cand, uint32_t* hist, int n, int r) {
    const int lane = threadIdx.x & 31;
    int hibin = -1;
    for (int pass = 0; pass < 2; pass++) {
        for (int i = lane; i < 256; i += 32) hist[i] = 0;
        __syncwarp();
        for (int i = lane; i < n; i += 32) {
            uint32_t k = cand[i];
            if (pass == 0) atomicAdd(&hist[k >> 8], 1u);
            else if ((int)(k >> 8) == hibin) atomicAdd(&hist[k & 255u], 1u);
        }
        __syncwarp();
        uint32_t bv[8];
        uint32_t loc = 0;
#pragma unroll
        for (int j = 0; j < 8; j++) { bv[j] = hist[lane * 8 + j]; loc += bv[j]; }
        uint32_t pre = loc;
#pragma unroll
        for (int d = 1; d < 32; d <<= 1) {
            uint32_t t = __shfl_up_sync(0xffffffffu, pre, d);
            if (lane >= d) pre += t;
        }
        int excl = (int)(pre - loc);
        bool myfind = (r >= excl) && (r < excl + (int)loc);
        uint32_t ball = __ballot_sync(0xffffffffu, myfind);
        int src = __ffs(ball) - 1;
        int bin_out = 0, rem_out = 0;
        if (myfind) {
            int rem = r - excl, bsel = 0;
            bool found = false;
#pragma unroll
            for (int j = 0; j < 8; j++) {
                if (!found) {
                    if (rem < (int)bv[j]) { bsel = j; found = true; }
                    else rem -= (int)bv[j];
                }
            }
            bin_out = lane * 8 + bsel;
            rem_out = rem;
        }
        int bin = __shfl_sync(0xffffffffu, bin_out, src);
        r       = __shfl_sync(0xffffffffu, rem_out, src);
        if (pass == 0) hibin = bin;
        else           hibin = (hibin << 8) | bin;
        __syncwarp();
    }
    return hibin;   // full 16-bit key
}

// Block-wide exact rank-r selection from global (fallback; rare).
__device__ float block_select_global(const float* __restrict__ x, int b, int c, int r,
                                     uint32_t* hist, int* bcast) {
    const int tid = threadIdx.x;
    uint32_t prefix = 0, done = 0;
    for (int shift = 24; shift >= 0; shift -= 8) {
        for (int i = tid; i < 256; i += NT) hist[i] = 0;
        __syncthreads();
        for (int t = tid; t < T_DIM; t += NT) {
            float v = x[((size_t)b * T_DIM + t) * C_DIM + c];
            uint32_t k = fkey(v);
            if ((k & done) == prefix) atomicAdd(&hist[(k >> shift) & 255u], 1u);
        }
        __syncthreads();
        if (tid == 0) {
            int rr = r, bin = 255;
            for (int j = 0; j < 256; j++) {
                if (rr < (int)hist[j]) { bin = j; break; }
                rr -= (int)hist[j];
            }
            bcast[0] = bin; bcast[1] = rr;
        }
        __syncthreads();
        prefix |= (uint32_t)bcast[0] << shift;
        r = bcast[1];
        done |= 0xFFu << shift;
        __syncthreads();
    }
    return fkey_inv(prefix);
}

__device__ __forceinline__ void load_group(const float4* __restrict__ xb, int g, int tid,
                                           float4* buf) {
    const int base = g * DEPTH * NT + tid;
#pragma unroll
    for (int k = 0; k < DEPTH; k++)
        buf[k] = __ldcs(&xb[base + k * NT]);
}

__device__ __forceinline__ void consume_group(
    const float4* buf, ull& s01, ull& s23, ull& q01, ull& q23,
    uint32_t& pkneg, uint32_t& pkbel, uint32_t* addr, const uint32_t* maxa)
{
#pragma unroll
    for (int k = 0; k < DEPTH; k++) {
        float v0 = buf[k].x, v1 = buf[k].y, v2 = buf[k].z, v3 = buf[k].w;
        ull v01, v23;
        asm("mov.b64 %0, {%1, %2};" : "=l"(v01) : "f"(v0), "f"(v1));
        asm("mov.b64 %0, {%1, %2};" : "=l"(v23) : "f"(v2), "f"(v3));
        asm("add.rn.f32x2 %0, %0, %1;" : "+l"(s01) : "l"(v01));
        asm("add.rn.f32x2 %0, %0, %1;" : "+l"(s23) : "l"(v23));
        asm("fma.rn.f32x2 %0, %1, %1, %0;" : "+l"(q01) : "l"(v01));
        asm("fma.rn.f32x2 %0, %1, %1, %0;" : "+l"(q23) : "l"(v23));
        int b0 = __float_as_int(v0), b1 = __float_as_int(v1);
        int b2 = __float_as_int(v2), b3 = __float_as_int(v3);
        // shift-first keys: overflow-safe (range +/-2^26); key<0 <=> x < LO exactly
        int k0 = (b0 >> 5) - (int)LO_S;
        int k1 = (b1 >> 5) - (int)LO_S;
        int k2 = (b2 >> 5) - (int)LO_S;
        int k3 = (b3 >> 5) - (int)LO_S;
        capture4(k0, k1, k2, k3, addr[0], addr[1], addr[2], addr[3],
                 maxa[0], maxa[1], maxa[2], maxa[3]);
        pkbel += sign4(k0, k1, k2, k3);   // exact below-window count
        pkneg += sign4(b0, b1, b2, b3);   // sign(x); cpos = 64 - neg per channel
    }
}

__global__ void __launch_bounds__(NT, 5) stat_kernel(
    const float* __restrict__ x, const float* __restrict__ W,
    const float* __restrict__ bias, float* __restrict__ out)
{
    extern __shared__ unsigned char smem_raw[];
    Sm* sm = reinterpret_cast<Sm*>(smem_raw);

    const int tid  = threadIdx.x;
    const int lane = tid & 31;
    const int wid  = tid >> 5;
    const int b    = blockIdx.x;

    if (tid < C_DIM) sm->fb[tid] = 0;
    __syncthreads();

    const int cbase = (tid & 1) * 4;   // even tids own ch 0-3, odd own ch 4-7

    uint32_t addr[4], maxa[4];
#pragma unroll
    for (int j = 0; j < 4; j++) {
        addr[j] = (uint32_t)__cvta_generic_to_shared(&sm->priv[0][j][tid]);
        maxa[j] = addr[j] + SLOTS * PLANE2;    // stores blocked at addr==maxa
    }

    // ---- Main streaming pass: rolled loop, peeled register double-buffer ----
    const float4* xb = reinterpret_cast<const float4*>(x + (size_t)b * T_DIM * C_DIM);
    ull s01 = 0, s23 = 0, q01 = 0, q23 = 0;
    uint32_t pkneg = 0, pkbel = 0;     // byte-packed counts (max 64 each)

    float4 A[DEPTH], Bf[DEPTH];
    load_group(xb, 0, tid, A);
#pragma unroll 1
    for (int g = 0; g < GROUPS - 2; g += 2) {
        load_group(xb, g + 1, tid, Bf);
        consume_group(A, s01, s23, q01, q23, pkneg, pkbel, addr, maxa);
        load_group(xb, g + 2, tid, A);
        consume_group(Bf, s01, s23, q01, q23, pkneg, pkbel, addr, maxa);
    }
    load_group(xb, GROUPS - 1, tid, Bf);
    consume_group(A, s01, s23, q01, q23, pkneg, pkbel, addr, maxa);
    consume_group(Bf, s01, s23, q01, q23, pkneg, pkbel, addr, maxa);

    // per-thread hit counts; cursor saturation (hits>=SLOTS) -> possible loss -> fallback
    {
        uint32_t pk = 0;
#pragma unroll
        for (int j = 0; j < 4; j++) {
            uint32_t hits = (addr[j] - (maxa[j] - SLOTS * PLANE2)) >> 11;  // PLANE2=2048
            if (hits >= SLOTS) sm->fb[cbase + j] = 1;
            pk |= hits << (8 * j);
        }
        sm->cntp[tid] = pk;
    }

    // unpack accumulators
    float sum[4], ssq[4];
    asm("mov.b64 {%0, %1}, %2;" : "=f"(sum[0]), "=f"(sum[1]) : "l"(s01));
    asm("mov.b64 {%0, %1}, %2;" : "=f"(sum[2]), "=f"(sum[3]) : "l"(s23));
    asm("mov.b64 {%0, %1}, %2;" : "=f"(ssq[0]), "=f"(ssq[1]) : "l"(q01));
    asm("mov.b64 {%0, %1}, %2;" : "=f"(ssq[2]), "=f"(ssq[3]) : "l"(q23));
    int cpos[4], cbel[4];
#pragma unroll
    for (int j = 0; j < 4; j++) {
        cpos[j] = 64 - (int)((pkneg >> (8 * j)) & 0xFFu);   // 64 elems per channel
        cbel[j] = (int)((pkbel >> (8 * j)) & 0xFFu);
    }

    // ---- parity-preserving warp reduction (masks 2..16 keep even/odd separate) ----
#pragma unroll
    for (int m = 2; m < 32; m <<= 1) {
#pragma unroll
        for (int j = 0; j < 4; j++) {
            sum[j]  += __shfl_xor_sync(0xffffffffu, sum[j], m);
            ssq[j]  += __shfl_xor_sync(0xffffffffu, ssq[j], m);
            cpos[j] += __shfl_xor_sync(0xffffffffu, cpos[j], m);
            cbel[j] += __shfl_xor_sync(0xffffffffu, cbel[j], m);
        }
    }
    if (lane < 2) {
#pragma unroll
        for (int j = 0; j < 4; j++) {
            int c = lane * 4 + j;
            sm->wpart[wid][c][0] = sum[j];
            sm->wpart[wid][c][1] = ssq[j];
            sm->wpart[wid][c][2] = (float)cpos[j];
            sm->wbelow[wid][c]   = cbel[j];
        }
    }
    __syncthreads();

    // ---- deterministic block combine ----
    if (tid < C_DIM) {
        float S = 0.f, Q = 0.f, P = 0.f; int Bl = 0;
        for (int w = 0; w < NWARPS; w++) {
            S  += sm->wpart[w][tid][0];
            Q  += sm->wpart[w][tid][1];
            P  += sm->wpart[w][tid][2];
            Bl += sm->wbelow[w][tid];
        }
        float mean = S / (float)T_DIM;
        float var  = (Q - S * S / (float)T_DIM) / (float)(T_DIM - 1);
        sm->stat[tid][1] = mean;
        sm->stat[tid][2] = P;
        sm->stat[tid][3] = sqrtf(fmaxf(var, 0.0f));
        sm->below[tid]   = Bl;
    }
    __syncthreads();

    // ---- per-channel compaction: priv slots -> cand list (warp c owns channel c) ----
    const int c   = wid;
    const int j   = c & 3;
    const int par = c >> 2;
    int nc = 0;
    int fbc = sm->fb[c];
    if (!fbc) {
#pragma unroll 1
        for (int i = lane; i < (NT / 2) * SLOTS; i += 32) {
            int tt   = i & (NT / 2 - 1);
            int slot = i >> 7;                    // NT/2 = 128
            int tid2 = (tt << 1) | par;
            uint32_t cnt = (sm->cntp[tid2] >> (j * 8)) & 0xFFu;
            bool valid = (uint32_t)slot < cnt;
            uint16_t v = sm->priv[slot][j][tid2];
            uint32_t m = __ballot_sync(0xffffffffu, valid);
            int pos = nc + __popc(m & ((1u << lane) - 1u));
            if (valid && pos < CAP) sm->cand[c][pos] = v;
            nc += __popc(m);
        }
    }
    __syncthreads();   // priv dead from here: radix hists alias it below

    // ---- per-channel quantile: 2-pass radix select on u16 keys ----
    uint32_t* histc = reinterpret_cast<uint32_t*>(&sm->priv[0][0][0]) + c * 256;
    {
        int cb = sm->below[c];
        int l0 = RANK0 - cb;
        bool ok = !fbc && (nc <= CAP) && (l0 >= 0) && (l0 + 1 < nc);
        if (ok) {
            int k0 = warp_select16(sm->cand[c], histc, nc, l0);
            int k1 = warp_select16(sm->cand[c], histc, nc, l0 + 1);
            if (lane == 0) {
                float v0 = key_to_float(k0), v1 = key_to_float(k1);
                sm->stat[c][0] = v0 + kFrac * (v1 - v0);
            }
        } else {
            if (lane == 0) sm->fb[c] = 1;
        }
    }
    __syncthreads();

    // ---- exact fallback (block-wide; rare). reuses aliased hist region ----
    for (int cc = 0; cc < C_DIM; cc++) {
        if (sm->fb[cc]) {
            uint32_t* h0 = reinterpret_cast<uint32_t*>(&sm->priv[0][0][0]);
            float v0 = block_select_global(x, b, cc, RANK0,     h0, sm->bcast);
            float v1 = block_select_global(x, b, cc, RANK0 + 1, h0, sm->bcast);
            if (tid == 0) sm->stat[cc][0] = v0 + kFrac * (v1 - v0);
            __syncthreads();
        }
    }

    // ---- tiny linear layer: feats order [q, mean, cnt, std] per channel ----
    if (tid < C_DIM) {
        float acc = sm->stat[tid][0] * __ldg(&W[tid * 4 + 0])
                  + sm->stat[tid][1] * __ldg(&W[tid * 4 + 1])
                  + sm->stat[tid][2] * __ldg(&W[tid * 4 + 2])
                  + sm->stat[tid][3] * __ldg(&W[tid * 4 + 3]);
        acc += __shfl_xor_sync(0xffu, acc, 1);
        acc += __shfl_xor_sync(0xffu, acc, 2);
        acc += __shfl_xor_sync(0xffu, acc, 4);
        if (tid == 0) out[b] = acc + __ldg(&bias[0]);
    }
}

extern "C" void kernel_launch(void* const* d_in, const int* in_sizes, int n_in,
                              void* d_out, int out_size) {
    const float* x    = (const float*)d_in[0];
    const float* W    = (const float*)d_in[1];
    const float* bias = (const float*)d_in[2];
    float* out        = (float*)d_out;
    int B = in_sizes[0] / (T_DIM * C_DIM);
    cudaFuncSetAttribute(stat_kernel, cudaFuncAttributeMaxDynamicSharedMemorySize,
                         (int)sizeof(Sm));
    stat_kernel<<<B, NT, sizeof(Sm)>>>(x, W, bias, out);
}